// round 2
// baseline (speedup 1.0000x reference)
#include <cuda_runtime.h>
#include <math.h>

#define L 64
#define R 4096
#define E 32
#define F 64
#define P 8

#define RTILE 256
#define NRT   (R / RTILE)   // 16

// RBF constants
#define DELTA      (10.0f / 31.0f)
#define INV_DELTA  (31.0f / 10.0f)
// KC = sqrt(log2(e)) / |sigma|, sigma = -0.3125  ->  exp(-z^2) = exp2(-(KC*(d-mu))^2)
#define KC         3.8435917081166394f
#define DK         (DELTA * KC)
#define WIN        2.0f      // |d-mu| > WIN -> rbf < 2e-18, safely dropped

// scratch: atn[e][l][r]  (33.5 MB, L2-resident) and per-block partials
__device__ float g_atn[E * L * R];
__device__ float g_part[L * NRT * P];

// ---------------------------------------------------------------------------
// Kernel A: atn[e][l][r] = sum_f lig[l][e][f] * rec[r][e][f]
// grid (E, NRT), 256 threads. C-tile 64l x 256r, micro-tile 8x8 per thread.
// smem: s_lig[64][64] (l-major), s_rec[64][257] (f-major transposed, padded)
// ---------------------------------------------------------------------------
__global__ __launch_bounds__(256) void atn_gemm(const float* __restrict__ lig,
                                                const float* __restrict__ rec) {
    const int e  = blockIdx.x;
    const int rt = blockIdx.y * RTILE;
    extern __shared__ float sm[];
    float* s_lig = sm;              // 64*64
    float* s_rec = sm + 64 * 64;    // 64 rows (f) * 257
    const int tid = threadIdx.x;

    // load lig[:, e, :] : 4096 floats
#pragma unroll
    for (int k = 0; k < 4; k++) {
        int idx = tid + (k << 8);         // float4 index
        int l = idx >> 4, f4 = idx & 15;
        float4 v = *(const float4*)(lig + ((l * E + e) << 6) + (f4 << 2));
        *(float4*)(s_lig + (l << 6) + (f4 << 2)) = v;
    }
    // load rec[rt:rt+256, e, :] transposed to f-major : 16384 floats
#pragma unroll
    for (int k = 0; k < 16; k++) {
        int idx = tid + (k << 8);
        int rl = idx >> 4, f4 = idx & 15;
        float4 v = *(const float4*)(rec + (((rt + rl) * E + e) << 6) + (f4 << 2));
        int f = f4 << 2;
        s_rec[(f + 0) * 257 + rl] = v.x;
        s_rec[(f + 1) * 257 + rl] = v.y;
        s_rec[(f + 2) * 257 + rl] = v.z;
        s_rec[(f + 3) * 257 + rl] = v.w;
    }
    __syncthreads();

    const int ly = tid >> 5;   // warp-uniform -> a loads broadcast
    const int rx = tid & 31;   // lane-consecutive -> b loads conflict-free

    float c[8][8];
#pragma unroll
    for (int i = 0; i < 8; i++)
#pragma unroll
        for (int j = 0; j < 8; j++) c[i][j] = 0.0f;

#pragma unroll 4
    for (int f = 0; f < F; f++) {
        float a[8], b[8];
#pragma unroll
        for (int i = 0; i < 8; i++) a[i] = s_lig[((ly << 3) + i) * 64 + f];
#pragma unroll
        for (int j = 0; j < 8; j++) b[j] = s_rec[f * 257 + rx + (j << 5)];
#pragma unroll
        for (int i = 0; i < 8; i++)
#pragma unroll
            for (int j = 0; j < 8; j++) c[i][j] = fmaf(a[i], b[j], c[i][j]);
    }

#pragma unroll
    for (int i = 0; i < 8; i++) {
        int l = (ly << 3) + i;
        int base = ((e << 6) + l) * R + rt + rx;
#pragma unroll
        for (int j = 0; j < 8; j++) g_atn[base + (j << 5)] = c[i][j];
    }
}

// ---------------------------------------------------------------------------
// Kernel B: windowed RBF accumulation.
// grid (L, NRT), 256 threads; thread <-> one r; 8 poses; e-window <= 13.
// ---------------------------------------------------------------------------
__global__ __launch_bounds__(256) void rbf_energy(const float* __restrict__ ligc,
                                                  const float* __restrict__ recc) {
    const int l   = blockIdx.x;
    const int rt  = blockIdx.y * RTILE;
    const int tid = threadIdx.x;

    __shared__ float s_a[E][256];   // atn tile, dynamic-e indexable
    __shared__ float s_lc[P][3];
    __shared__ float s_red[8][P];

    if (tid < P * 3) {
        int p = tid / 3, cc = tid % 3;
        s_lc[p][cc] = ligc[p * (L * 3) + l * 3 + cc];
    }
#pragma unroll
    for (int e = 0; e < E; e++)
        s_a[e][tid] = g_atn[(e * L + l) * R + rt + tid];
    __syncthreads();

    const int r = rt + tid;
    const float cx = recc[3 * r + 0];
    const float cy = recc[3 * r + 1];
    const float cz = recc[3 * r + 2];

    float acc[P];
#pragma unroll
    for (int p = 0; p < P; p++) {
        float dx = s_lc[p][0] - cx;
        float dy = s_lc[p][1] - cy;
        float dz = s_lc[p][2] - cz;
        // eps added per-coordinate before sum, as in reference: +3*1e-10
        float d2 = fmaf(dx, dx, fmaf(dy, dy, fmaf(dz, dz, 3.0e-10f)));
        float d  = sqrtf(d2);

        int elo = (int)ceilf((d - WIN) * INV_DELTA);
        if (elo < 0) elo = 0;
        int ehi = (int)floorf((d + WIN) * INV_DELTA);
        if (ehi > E - 1) ehi = E - 1;

        float s  = (d - (float)elo * DELTA) * KC;
        float ap = 0.0f;
        for (int e = elo; e <= ehi; e++) {
            float t = -s * s;
            float rbf;
            asm("ex2.approx.ftz.f32 %0, %1;" : "=f"(rbf) : "f"(t));
            ap = fmaf(s_a[e][tid], rbf, ap);
            s -= DK;
        }
        acc[p] = ap;
    }

    // deterministic block reduction
#pragma unroll
    for (int p = 0; p < P; p++) {
        float v = acc[p];
#pragma unroll
        for (int off = 16; off; off >>= 1)
            v += __shfl_down_sync(0xffffffffu, v, off);
        if ((tid & 31) == 0) s_red[tid >> 5][p] = v;
    }
    __syncthreads();
    if (tid < P) {
        float v = 0.0f;
#pragma unroll
        for (int w = 0; w < 8; w++) v += s_red[w][tid];
        g_part[(l * NRT + blockIdx.y) * P + tid] = v;
    }
}

// ---------------------------------------------------------------------------
// Kernel C: reduce partials, apply weight/bias
// ---------------------------------------------------------------------------
__global__ __launch_bounds__(256) void finalize_k(const float* __restrict__ w,
                                                  const float* __restrict__ b,
                                                  float* __restrict__ out) {
    const int p    = threadIdx.x >> 5;   // 8 warps -> 8 poses
    const int lane = threadIdx.x & 31;
    float s = 0.0f;
    for (int k = lane; k < L * NRT; k += 32) s += g_part[k * P + p];
#pragma unroll
    for (int off = 16; off; off >>= 1)
        s += __shfl_down_sync(0xffffffffu, s, off);
    if (lane == 0) out[p] = fmaf(s, *w, *b);
}

// ---------------------------------------------------------------------------
extern "C" void kernel_launch(void* const* d_in, const int* in_sizes, int n_in,
                              void* d_out, int out_size) {
    const float* lig_feat   = (const float*)d_in[0];
    const float* rec_feat   = (const float*)d_in[1];
    const float* lig_coords = (const float*)d_in[2];
    const float* rec_coord  = (const float*)d_in[3];
    const float* weight     = (const float*)d_in[4];
    const float* bias       = (const float*)d_in[5];
    float* out = (float*)d_out;

    const int smem = (64 * 64 + 64 * 257) * (int)sizeof(float);  // 82176 B
    cudaFuncSetAttribute(atn_gemm, cudaFuncAttributeMaxDynamicSharedMemorySize, smem);

    atn_gemm  <<<dim3(E, NRT), 256, smem>>>(lig_feat, rec_feat);
    rbf_energy<<<dim3(L, NRT), 256>>>(lig_coords, rec_coord);
    finalize_k<<<1, 256>>>(weight, bias, out);
}